// round 1
// baseline (speedup 1.0000x reference)
#include <cuda_runtime.h>

// Problem constants
#define PB 16384   // batch
#define PN 32      // keypoints
#define PK 16      // mixture components
// D = 3

#define MB 8       // samples per thread
#define TPB 256    // threads per block

// Per-(n,k) params, SoA layout [k][field][n], field: 0..2 mean, 3..8 prec (p00,p01,p02,p11,p12,p22), 9 lc
__device__ float g_params[PK * 10 * PN];

__global__ void precompute_params(const float* __restrict__ means,
                                  const float* __restrict__ covs,
                                  const float* __restrict__ weights) {
    int t = threadIdx.x;            // 0..511
    if (t >= PN * PK) return;
    int n = t & 31;
    int k = t >> 5;
    int nk = n * PK + k;

    const float* c = covs + nk * 9;
    float c00 = c[0], c01 = c[1], c02 = c[2];
    float c11 = c[4], c12 = c[5], c22 = c[8];

    // cofactors (symmetric input)
    float m00 = c11 * c22 - c12 * c12;
    float m01 = c02 * c12 - c01 * c22;
    float m02 = c01 * c12 - c02 * c11;
    float det = c00 * m00 + c01 * m01 + c02 * m02;
    float inv = 1.0f / det;

    float p00 = m00 * inv;
    float p01 = m01 * inv;
    float p02 = m02 * inv;
    float p11 = (c00 * c22 - c02 * c02) * inv;
    float p12 = (c01 * c02 - c00 * c12) * inv;
    float p22 = (c00 * c11 - c01 * c01) * inv;

    // lc = log2( w / sqrt((2*pi)^3 * det) )
    const float TWOPI3 = 248.05021344239853f;
    float lc = log2f(weights[nk]) - 0.5f * log2f(TWOPI3 * det);

    const float* mu = means + nk * 3;
    float* base = g_params + k * 10 * PN + n;
    base[0 * PN] = mu[0];
    base[1 * PN] = mu[1];
    base[2 * PN] = mu[2];
    base[3 * PN] = p00;
    base[4 * PN] = p01;
    base[5 * PN] = p02;
    base[6 * PN] = p11;
    base[7 * PN] = p12;
    base[8 * PN] = p22;
    base[9 * PN] = lc;
}

__device__ __forceinline__ float ex2_approx(float x) {
    float r;
    asm("ex2.approx.ftz.f32 %0, %1;" : "=f"(r) : "f"(x));
    return r;
}

__global__ void __launch_bounds__(TPB) gmm_main(const float* __restrict__ kps,
                                                float* __restrict__ out) {
    int tid = blockIdx.x * TPB + threadIdx.x;   // 0 .. B/MB*N - 1
    int n  = tid & 31;          // lane = keypoint index -> coalesced I/O
    int bg = tid >> 5;          // batch group
    int b0 = bg * MB;

    float x[MB], y[MB], z[MB];
#pragma unroll
    for (int i = 0; i < MB; i++) {
        const float* p = kps + ((b0 + i) * PN + n) * 3;
        x[i] = p[0]; y[i] = p[1]; z[i] = p[2];
    }

    float pdf[MB], gx[MB], gy[MB], gz[MB];
#pragma unroll
    for (int i = 0; i < MB; i++) { pdf[i] = 0.0f; gx[i] = 0.0f; gy[i] = 0.0f; gz[i] = 0.0f; }

    const float NEG_HALF_L2E = -0.72134752044448170f;  // -0.5 * log2(e)

#pragma unroll 2
    for (int k = 0; k < PK; k++) {
        const float* pp = g_params + k * 10 * PN + n;
        float mx  = __ldg(pp + 0 * PN);
        float my  = __ldg(pp + 1 * PN);
        float mz  = __ldg(pp + 2 * PN);
        float p00 = __ldg(pp + 3 * PN);
        float p01 = __ldg(pp + 4 * PN);
        float p02 = __ldg(pp + 5 * PN);
        float p11 = __ldg(pp + 6 * PN);
        float p12 = __ldg(pp + 7 * PN);
        float p22 = __ldg(pp + 8 * PN);
        float lc  = __ldg(pp + 9 * PN);

#pragma unroll
        for (int i = 0; i < MB; i++) {
            float d0 = x[i] - mx;
            float d1 = y[i] - my;
            float d2 = z[i] - mz;
            float pd0 = fmaf(p00, d0, fmaf(p01, d1, p02 * d2));
            float pd1 = fmaf(p01, d0, fmaf(p11, d1, p12 * d2));
            float pd2 = fmaf(p02, d0, fmaf(p12, d1, p22 * d2));
            float maha = fmaf(pd0, d0, fmaf(pd1, d1, pd2 * d2));
            float e = ex2_approx(fmaf(maha, NEG_HALF_L2E, lc));
            pdf[i] += e;
            gx[i] = fmaf(e, pd0, gx[i]);
            gy[i] = fmaf(e, pd1, gy[i]);
            gz[i] = fmaf(e, pd2, gz[i]);
        }
    }

    // epilogue constants
    const float L2E_OVER_TAU  = 0.19235933878519513f;   // log2(e)/7.5
    const float L2E_OVER_1100 = 0.0013115409462626940f; // log2(e)/1100
    float* out_grad = out + (size_t)PB * PN * 3;

#pragma unroll
    for (int i = 0; i < MB; i++) {
        int b = b0 + i;
        // density sigmoid: s = 1/(1+exp(-(pdf-40)/7.5)) = 1/(1 + 2^((40-pdf)*log2e/7.5))
        float u = ex2_approx((40.0f - pdf[i]) * L2E_OVER_TAU);
        float s = 1.0f / (1.0f + u);

        // gradient: grad = -sum e*pd (accumulated positive -> negate)
        float s2 = fmaf(gx[i], gx[i], fmaf(gy[i], gy[i], gz[i] * gz[i]));
        float rinv = rsqrtf(s2);
        float gn = s2 * rinv;                      // |grad|
        float mag = ex2_approx((5500.0f - gn) * L2E_OVER_1100);
        float scale = -rinv * mag;                 // ETA = 1, includes negation

        float* od = out + ((size_t)b * PN + n) * 3;
        od[0] = s; od[1] = s; od[2] = s;
        float* og = out_grad + ((size_t)b * PN + n) * 3;
        og[0] = gx[i] * scale;
        og[1] = gy[i] * scale;
        og[2] = gz[i] * scale;
    }
}

extern "C" void kernel_launch(void* const* d_in, const int* in_sizes, int n_in,
                              void* d_out, int out_size) {
    const float* kps     = (const float*)d_in[0];
    const float* means   = (const float*)d_in[1];
    const float* covs    = (const float*)d_in[2];
    const float* weights = (const float*)d_in[3];
    float* out = (float*)d_out;

    precompute_params<<<1, 512>>>(means, covs, weights);

    int total_threads = (PB / MB) * PN;   // 65536
    gmm_main<<<total_threads / TPB, TPB>>>(kps, out);
}

// round 2
// speedup vs baseline: 1.0103x; 1.0103x over previous
#include <cuda_runtime.h>

// Problem constants
#define PB 16384   // batch
#define PN 32      // keypoints
#define PK 16      // mixture components
// D = 3

#define MB  8      // samples per thread
#define NP  (MB/2) // f32x2 pairs per thread
#define TPB 256

typedef unsigned long long u64;

__device__ __forceinline__ u64 pk2(float lo, float hi) {
    u64 r; asm("mov.b64 %0,{%1,%2};" : "=l"(r) : "f"(lo), "f"(hi)); return r;
}
__device__ __forceinline__ void up2(u64 v, float& lo, float& hi) {
    asm("mov.b64 {%0,%1},%2;" : "=f"(lo), "=f"(hi) : "l"(v));
}
__device__ __forceinline__ u64 fma2(u64 a, u64 b, u64 c) {
    u64 d; asm("fma.rn.f32x2 %0,%1,%2,%3;" : "=l"(d) : "l"(a), "l"(b), "l"(c)); return d;
}
__device__ __forceinline__ u64 add2(u64 a, u64 b) {
    u64 d; asm("add.rn.f32x2 %0,%1,%2;" : "=l"(d) : "l"(a), "l"(b)); return d;
}
__device__ __forceinline__ u64 mul2(u64 a, u64 b) {
    u64 d; asm("mul.rn.f32x2 %0,%1,%2;" : "=l"(d) : "l"(a), "l"(b)); return d;
}
__device__ __forceinline__ float ex2a(float x) {
    float r; asm("ex2.approx.ftz.f32 %0,%1;" : "=f"(r) : "f"(x)); return r;
}

// smem params, broadcast-duplicated f32x2: [k][field][n]
// field 0..2: -mean ; 3..8: precision * (-0.5*log2 e) (q00,q01,q02,q11,q12,q22) ; 9: lc
__global__ void __launch_bounds__(TPB) gmm_fused(const float* __restrict__ kps,
                                                 const float* __restrict__ means,
                                                 const float* __restrict__ covs,
                                                 const float* __restrict__ weights,
                                                 float* __restrict__ out) {
    __shared__ u64 sp[PK * 10 * PN];   // 40 KB

    int tid = threadIdx.x;

    // ---- per-block param precompute (redundant across blocks, ~cheap) ----
    const float NH = -0.72134752044448170f;  // -(0.5 * log2 e)
    for (int t = tid; t < PN * PK; t += TPB) {
        int n = t & 31;
        int k = t >> 5;
        int nk = n * PK + k;

        const float* c = covs + nk * 9;
        float c00 = c[0], c01 = c[1], c02 = c[2];
        float c11 = c[4], c12 = c[5], c22 = c[8];

        float m00 = c11 * c22 - c12 * c12;
        float m01 = c02 * c12 - c01 * c22;
        float m02 = c01 * c12 - c02 * c11;
        float det = c00 * m00 + c01 * m01 + c02 * m02;
        float inv = NH / det;    // fold the -0.5*log2e scale into the inverse

        float q00 = m00 * inv;
        float q01 = m01 * inv;
        float q02 = m02 * inv;
        float q11 = (c00 * c22 - c02 * c02) * inv;
        float q12 = (c01 * c02 - c00 * c12) * inv;
        float q22 = (c00 * c11 - c01 * c01) * inv;

        const float TWOPI3 = 248.05021344239853f;  // (2*pi)^3
        float lc = log2f(weights[nk]) - 0.5f * log2f(TWOPI3 * det);

        const float* mu = means + nk * 3;
        u64* base = sp + k * 10 * PN + n;
        base[0 * PN] = pk2(-mu[0], -mu[0]);
        base[1 * PN] = pk2(-mu[1], -mu[1]);
        base[2 * PN] = pk2(-mu[2], -mu[2]);
        base[3 * PN] = pk2(q00, q00);
        base[4 * PN] = pk2(q01, q01);
        base[5 * PN] = pk2(q02, q02);
        base[6 * PN] = pk2(q11, q11);
        base[7 * PN] = pk2(q12, q12);
        base[8 * PN] = pk2(q22, q22);
        base[9 * PN] = pk2(lc, lc);
    }
    __syncthreads();

    // ---- main compute ----
    int gtid = blockIdx.x * TPB + tid;
    int n  = gtid & 31;      // lane = keypoint -> coalesced I/O
    int bg = gtid >> 5;
    int b0 = bg * MB;

    u64 X[NP], Y[NP], Z[NP];
#pragma unroll
    for (int p = 0; p < NP; p++) {
        const float* a = kps + ((b0 + 2 * p)     * PN + n) * 3;
        const float* b = kps + ((b0 + 2 * p + 1) * PN + n) * 3;
        X[p] = pk2(a[0], b[0]);
        Y[p] = pk2(a[1], b[1]);
        Z[p] = pk2(a[2], b[2]);
    }

    u64 PDF[NP], GX[NP], GY[NP], GZ[NP];
    u64 zero = pk2(0.0f, 0.0f);
#pragma unroll
    for (int p = 0; p < NP; p++) { PDF[p] = zero; GX[p] = zero; GY[p] = zero; GZ[p] = zero; }

#pragma unroll 4
    for (int k = 0; k < PK; k++) {
        const u64* pp = sp + k * 10 * PN + n;
        u64 nmx = pp[0 * PN];
        u64 nmy = pp[1 * PN];
        u64 nmz = pp[2 * PN];
        u64 q00 = pp[3 * PN];
        u64 q01 = pp[4 * PN];
        u64 q02 = pp[5 * PN];
        u64 q11 = pp[6 * PN];
        u64 q12 = pp[7 * PN];
        u64 q22 = pp[8 * PN];
        u64 lc  = pp[9 * PN];

#pragma unroll
        for (int p = 0; p < NP; p++) {
            u64 d0 = add2(X[p], nmx);
            u64 d1 = add2(Y[p], nmy);
            u64 d2 = add2(Z[p], nmz);
            // pd = (-0.5*log2e) * Sigma^{-1} (x-mu)
            u64 pd0 = fma2(q00, d0, fma2(q01, d1, mul2(q02, d2)));
            u64 pd1 = fma2(q01, d0, fma2(q11, d1, mul2(q12, d2)));
            u64 pd2 = fma2(q02, d0, fma2(q12, d1, mul2(q22, d2)));
            // earg = (-0.5*log2e)*maha + lc  (lc folded into the chain)
            u64 earg = fma2(pd0, d0, fma2(pd1, d1, fma2(pd2, d2, lc)));
            float elo, ehi;
            up2(earg, elo, ehi);
            u64 e = pk2(ex2a(elo), ex2a(ehi));
            PDF[p] = add2(PDF[p], e);
            GX[p] = fma2(e, pd0, GX[p]);
            GY[p] = fma2(e, pd1, GY[p]);
            GZ[p] = fma2(e, pd2, GZ[p]);
        }
    }

    // ---- epilogue ----
    // gacc = sum e * pd' = (0.5*log2e) * grad_true  (positive multiple -> same direction)
    // |grad_true| = |gacc| / (0.5*log2e); with (log2e/1100)/(0.5*log2e) = 1/550 exactly:
    //   mag = 2^(5*log2e - |gacc|/550)
    const float L2E_OVER_TAU = 0.19235933878519513f;   // log2e / 7.5
    const float MAG_C0 = 7.2134752044448170f;          // 5 * log2 e
    const float MAG_C1 = -1.0f / 550.0f;
    float* out_grad = out + (size_t)PB * PN * 3;

#pragma unroll
    for (int p = 0; p < NP; p++) {
        float pf[2], ax[2], ay[2], az[2];
        up2(PDF[p], pf[0], pf[1]);
        up2(GX[p],  ax[0], ax[1]);
        up2(GY[p],  ay[0], ay[1]);
        up2(GZ[p],  az[0], az[1]);
#pragma unroll
        for (int h = 0; h < 2; h++) {
            int b = b0 + 2 * p + h;
            // density sigmoid
            float u = ex2a((40.0f - pf[h]) * L2E_OVER_TAU);
            float s = __fdividef(1.0f, 1.0f + u);

            float s2 = fmaf(ax[h], ax[h], fmaf(ay[h], ay[h], az[h] * az[h]));
            float rinv = rsqrtf(s2);
            float gs = s2 * rinv;                       // |gacc|
            float mag = ex2a(fmaf(gs, MAG_C1, MAG_C0));
            float scale = rinv * mag;                   // ETA=1; sign already correct

            float* od = out + ((size_t)b * PN + n) * 3;
            od[0] = s; od[1] = s; od[2] = s;
            float* og = out_grad + ((size_t)b * PN + n) * 3;
            og[0] = ax[h] * scale;
            og[1] = ay[h] * scale;
            og[2] = az[h] * scale;
        }
    }
}

extern "C" void kernel_launch(void* const* d_in, const int* in_sizes, int n_in,
                              void* d_out, int out_size) {
    const float* kps     = (const float*)d_in[0];
    const float* means   = (const float*)d_in[1];
    const float* covs    = (const float*)d_in[2];
    const float* weights = (const float*)d_in[3];
    float* out = (float*)d_out;

    int total_threads = (PB / MB) * PN;   // 65536
    gmm_fused<<<total_threads / TPB, TPB>>>(kps, means, covs, weights, out);
}